// round 3
// baseline (speedup 1.0000x reference)
#include <cuda_runtime.h>
#include <cstdint>

#define B_   8
#define C_   256
#define HW_  16384
#define NG_  524288.0f
#define LDX  68
#define LDW  36
#define LDP  36

// scratch (device globals; allocation APIs forbidden)
__device__ float g_q[(size_t)B_ * C_ * HW_];
__device__ float g_k[(size_t)B_ * C_ * HW_];
__device__ float g_v[(size_t)B_ * C_ * HW_];
__device__ float g_kvp[(size_t)B_ * 16 * C_ * C_];
__device__ float g_kvn[B_ * C_ * C_];
__device__ float g_M[B_ * C_ * C_];
__device__ float g_ksum[B_ * C_];
__device__ float g_sum[B_ * 8];
__device__ float g_sq[B_ * 8];

__device__ __forceinline__ float to_tf32(float x) {
    uint32_t u; asm("cvt.rna.tf32.f32 %0, %1;" : "=r"(u) : "f"(x));
    return __uint_as_float(u);
}
__device__ __forceinline__ float elu1(float x) { return x > 0.f ? x + 1.f : __expf(x); }
__device__ __forceinline__ void mma8(float c[4], const uint32_t a[4], const uint32_t b[2]) {
    asm volatile("mma.sync.aligned.m16n8k8.row.col.f32.tf32.tf32.f32 "
        "{%0,%1,%2,%3},{%4,%5,%6,%7},{%8,%9},{%0,%1,%2,%3};\n"
        : "+f"(c[0]), "+f"(c[1]), "+f"(c[2]), "+f"(c[3])
        : "r"(a[0]), "r"(a[1]), "r"(a[2]), "r"(a[3]), "r"(b[0]), "r"(b[1]));
}

// C[256,64] = W[256,256] @ Xs[256,LDX]; warp tile 64x32 (4x2 warps), dbl-buffered W chunks
__device__ void gemm_tile(const float* __restrict__ Wg, const float* __restrict__ Xs,
                          float* Wbuf, int tid, int lane, int wo, int wp, float acc[4][4][4]) {
#pragma unroll
    for (int m = 0; m < 4; m++)
#pragma unroll
        for (int n = 0; n < 4; n++)
#pragma unroll
            for (int i = 0; i < 4; i++) acc[m][n][i] = 0.f;
    float4 r[8];
#pragma unroll
    for (int i = 0; i < 8; i++) {
        int lin = i * 256 + tid, o = lin >> 3, k4 = (lin & 7) << 2;
        r[i] = *(const float4*)(Wg + o * 256 + k4);
    }
#pragma unroll
    for (int i = 0; i < 8; i++) {
        int lin = i * 256 + tid, o = lin >> 3, k4 = (lin & 7) << 2;
        float4 v = r[i];
        v.x = to_tf32(v.x); v.y = to_tf32(v.y); v.z = to_tf32(v.z); v.w = to_tf32(v.w);
        *(float4*)(Wbuf + o * LDW + k4) = v;
    }
    __syncthreads();
    for (int kc = 0; kc < 8; kc++) {
        if (kc < 7) {
#pragma unroll
            for (int i = 0; i < 8; i++) {
                int lin = i * 256 + tid, o = lin >> 3, k4 = (lin & 7) << 2;
                r[i] = *(const float4*)(Wg + o * 256 + (kc + 1) * 32 + k4);
            }
        }
        const float* Wc = Wbuf + (kc & 1) * (256 * LDW);
#pragma unroll
        for (int ks = 0; ks < 4; ks++) {
            int kk = ks * 8 + (lane & 3);
            uint32_t a[4][4];
#pragma unroll
            for (int m = 0; m < 4; m++) {
                int row = wo * 64 + m * 16 + (lane >> 2);
                a[m][0] = __float_as_uint(Wc[row * LDW + kk]);
                a[m][1] = __float_as_uint(Wc[(row + 8) * LDW + kk]);
                a[m][2] = __float_as_uint(Wc[row * LDW + kk + 4]);
                a[m][3] = __float_as_uint(Wc[(row + 8) * LDW + kk + 4]);
            }
            uint32_t bf[4][2];
#pragma unroll
            for (int n = 0; n < 4; n++) {
                int col = wp * 32 + n * 8 + (lane >> 2);
                int kg = kc * 32 + ks * 8 + (lane & 3);
                bf[n][0] = __float_as_uint(Xs[kg * LDX + col]);
                bf[n][1] = __float_as_uint(Xs[(kg + 4) * LDX + col]);
            }
#pragma unroll
            for (int m = 0; m < 4; m++)
#pragma unroll
                for (int n = 0; n < 4; n++) mma8(acc[m][n], a[m], bf[n]);
        }
        if (kc < 7) {
            float* Wn = Wbuf + ((kc + 1) & 1) * (256 * LDW);
#pragma unroll
            for (int i = 0; i < 8; i++) {
                int lin = i * 256 + tid, o = lin >> 3, k4 = (lin & 7) << 2;
                float4 v = r[i];
                v.x = to_tf32(v.x); v.y = to_tf32(v.y); v.z = to_tf32(v.z); v.w = to_tf32(v.w);
                *(float4*)(Wn + o * LDW + k4) = v;
            }
        }
        __syncthreads();
    }
}

__global__ void k0_zero() {
    int i = threadIdx.x;
    if (i < 64) { g_sum[i] = 0.f; g_sq[i] = 0.f; }
}

__global__ void __launch_bounds__(256) k_stats(const float* __restrict__ x) {
    int bg = blockIdx.y;
    const float* base = x + (size_t)bg * 524288 + blockIdx.x * 32768;
    int tid = threadIdx.x, lane = tid & 31, warp = tid >> 5;
    float s = 0.f, sq = 0.f;
    for (int i = tid; i < 8192; i += 256) {
        float4 v = *(const float4*)(base + i * 4);
        s += v.x + v.y + v.z + v.w;
        sq = fmaf(v.x, v.x, sq); sq = fmaf(v.y, v.y, sq);
        sq = fmaf(v.z, v.z, sq); sq = fmaf(v.w, v.w, sq);
    }
#pragma unroll
    for (int o = 16; o > 0; o >>= 1) {
        s += __shfl_xor_sync(~0u, s, o); sq += __shfl_xor_sync(~0u, sq, o);
    }
    __shared__ float rs[8], rq[8];
    if (lane == 0) { rs[warp] = s; rq[warp] = sq; }
    __syncthreads();
    if (tid == 0) {
        float S = 0.f, Q = 0.f;
#pragma unroll
        for (int i = 0; i < 8; i++) { S += rs[i]; Q += rq[i]; }
        atomicAdd(&g_sum[bg], S); atomicAdd(&g_sq[bg], Q);
    }
}

// fused GN + Q/K/V 1x1 convs; writes g_q (elu+1), g_k (elu+1), g_v
__global__ void __launch_bounds__(256, 1) k_qkv(
    const float* __restrict__ x, const float* __restrict__ gamma, const float* __restrict__ beta,
    const float* __restrict__ Wq, const float* __restrict__ bq,
    const float* __restrict__ Wk, const float* __restrict__ bk,
    const float* __restrict__ Wv, const float* __restrict__ bv) {
    extern __shared__ float sm[];
    float* Xs = sm;
    float* Wbuf = sm + 256 * LDX;
    float* sc = Wbuf + 2 * 256 * LDW;
    float* tb = sc + 256;
    int b = blockIdx.y, p0 = blockIdx.x * 64;
    int tid = threadIdx.x, lane = tid & 31, warp = tid >> 5;
    int wo = warp & 3, wp = warp >> 2;
    {
        int c = tid, g = c >> 5;
        float mean = g_sum[b * 8 + g] * (1.0f / NG_);
        float var = g_sq[b * 8 + g] * (1.0f / NG_) - mean * mean;
        float s = rsqrtf(var + 1e-5f) * gamma[c];
        sc[c] = s; tb[c] = beta[c] - mean * s;
    }
    __syncthreads();
#pragma unroll
    for (int i = 0; i < 16; i++) {
        int lin = i * 256 + tid, c = lin >> 4, p4 = (lin & 15) << 2;
        float4 v = *(const float4*)(x + ((size_t)(b * C_ + c)) * HW_ + p0 + p4);
        float s = sc[c], t = tb[c];
        v.x = to_tf32(fmaf(v.x, s, t)); v.y = to_tf32(fmaf(v.y, s, t));
        v.z = to_tf32(fmaf(v.z, s, t)); v.w = to_tf32(fmaf(v.w, s, t));
        *(float4*)(Xs + c * LDX + p4) = v;
    }
    float acc[4][4][4];
    // Q
    gemm_tile(Wq, Xs, Wbuf, tid, lane, wo, wp, acc);
#pragma unroll
    for (int m = 0; m < 4; m++) {
        int row = wo * 64 + m * 16 + (lane >> 2);
        float b0 = bq[row], b1 = bq[row + 8];
        size_t o0 = ((size_t)(b * C_ + row)) * HW_ + p0;
        size_t o1 = ((size_t)(b * C_ + row + 8)) * HW_ + p0;
#pragma unroll
        for (int n = 0; n < 4; n++) {
            int col = wp * 32 + n * 8 + ((lane & 3) << 1);
            *(float2*)(g_q + o0 + col) = make_float2(elu1(acc[m][n][0] + b0), elu1(acc[m][n][1] + b0));
            *(float2*)(g_q + o1 + col) = make_float2(elu1(acc[m][n][2] + b1), elu1(acc[m][n][3] + b1));
        }
    }
    // K
    gemm_tile(Wk, Xs, Wbuf, tid, lane, wo, wp, acc);
#pragma unroll
    for (int m = 0; m < 4; m++) {
        int row = wo * 64 + m * 16 + (lane >> 2);
        float b0 = bk[row], b1 = bk[row + 8];
        size_t o0 = ((size_t)(b * C_ + row)) * HW_ + p0;
        size_t o1 = ((size_t)(b * C_ + row + 8)) * HW_ + p0;
#pragma unroll
        for (int n = 0; n < 4; n++) {
            int col = wp * 32 + n * 8 + ((lane & 3) << 1);
            *(float2*)(g_k + o0 + col) = make_float2(elu1(acc[m][n][0] + b0), elu1(acc[m][n][1] + b0));
            *(float2*)(g_k + o1 + col) = make_float2(elu1(acc[m][n][2] + b1), elu1(acc[m][n][3] + b1));
        }
    }
    // V
    gemm_tile(Wv, Xs, Wbuf, tid, lane, wo, wp, acc);
#pragma unroll
    for (int m = 0; m < 4; m++) {
        int row = wo * 64 + m * 16 + (lane >> 2);
        float b0 = bv[row], b1 = bv[row + 8];
        size_t o0 = ((size_t)(b * C_ + row)) * HW_ + p0;
        size_t o1 = ((size_t)(b * C_ + row + 8)) * HW_ + p0;
#pragma unroll
        for (int n = 0; n < 4; n++) {
            int col = wp * 32 + n * 8 + ((lane & 3) << 1);
            *(float2*)(g_v + o0 + col) = make_float2(acc[m][n][0] + b0, acc[m][n][1] + b0);
            *(float2*)(g_v + o1 + col) = make_float2(acc[m][n][2] + b1, acc[m][n][3] + b1);
        }
    }
}

__global__ void __launch_bounds__(128) k_ksum() {
    const float* base = g_k + (size_t)blockIdx.x * HW_;
    int tid = threadIdx.x, lane = tid & 31, warp = tid >> 5;
    float s = 0.f;
    for (int i = tid * 4; i < HW_; i += 512) {
        float4 v = *(const float4*)(base + i);
        s += v.x + v.y + v.z + v.w;
    }
#pragma unroll
    for (int o = 16; o > 0; o >>= 1) s += __shfl_xor_sync(~0u, s, o);
    __shared__ float rs[4];
    if (lane == 0) rs[warp] = s;
    __syncthreads();
    if (tid == 0) g_ksum[blockIdx.x] = rs[0] + rs[1] + rs[2] + rs[3];
}

// kv split-K: block(b, s, cvt): kvp[b][s][0:256][cv0:cv0+64] over 1024 pixels
__global__ void __launch_bounds__(256, 2) k_kv() {
    __shared__ float Ks[256 * LDP];
    __shared__ float Vs[64 * LDP];
    int s = blockIdx.x >> 2, cvt = blockIdx.x & 3, b = blockIdx.y;
    int cv0 = cvt * 64;
    int tid = threadIdx.x, lane = tid & 31, warp = tid >> 5;
    int wo = warp & 3, wp = warp >> 2;
    float acc[4][4][4];
#pragma unroll
    for (int m = 0; m < 4; m++)
#pragma unroll
        for (int n = 0; n < 4; n++)
#pragma unroll
            for (int i = 0; i < 4; i++) acc[m][n][i] = 0.f;
    for (int ch = 0; ch < 32; ch++) {
        int p0 = s * 1024 + ch * 32;
#pragma unroll
        for (int i = 0; i < 8; i++) {
            int lin = i * 256 + tid, c = lin >> 3, p4 = (lin & 7) << 2;
            float4 v = *(const float4*)(g_k + ((size_t)(b * C_ + c)) * HW_ + p0 + p4);
            v.x = to_tf32(v.x); v.y = to_tf32(v.y); v.z = to_tf32(v.z); v.w = to_tf32(v.w);
            *(float4*)(Ks + c * LDP + p4) = v;
        }
#pragma unroll
        for (int i = 0; i < 2; i++) {
            int lin = i * 256 + tid, c = lin >> 3, p4 = (lin & 7) << 2;
            float4 v = *(const float4*)(g_v + ((size_t)(b * C_ + cv0 + c)) * HW_ + p0 + p4);
            v.x = to_tf32(v.x); v.y = to_tf32(v.y); v.z = to_tf32(v.z); v.w = to_tf32(v.w);
            *(float4*)(Vs + c * LDP + p4) = v;
        }
        __syncthreads();
#pragma unroll
        for (int ks = 0; ks < 4; ks++) {
            int kk = ks * 8 + (lane & 3);
            uint32_t a[4][4];
#pragma unroll
            for (int m = 0; m < 4; m++) {
                int row = wo * 64 + m * 16 + (lane >> 2);
                a[m][0] = __float_as_uint(Ks[row * LDP + kk]);
                a[m][1] = __float_as_uint(Ks[(row + 8) * LDP + kk]);
                a[m][2] = __float_as_uint(Ks[row * LDP + kk + 4]);
                a[m][3] = __float_as_uint(Ks[(row + 8) * LDP + kk + 4]);
            }
            uint32_t bf[4][2];
#pragma unroll
            for (int n = 0; n < 4; n++) {
                int col = wp * 32 + n * 8 + (lane >> 2);
                bf[n][0] = __float_as_uint(Vs[col * LDP + kk]);
                bf[n][1] = __float_as_uint(Vs[col * LDP + kk + 4]);
            }
#pragma unroll
            for (int m = 0; m < 4; m++)
#pragma unroll
                for (int n = 0; n < 4; n++) mma8(acc[m][n], a[m], bf[n]);
        }
        __syncthreads();
    }
    float* outp = g_kvp + ((size_t)(b * 16 + s)) * C_ * C_;
#pragma unroll
    for (int m = 0; m < 4; m++) {
        int row = wo * 64 + m * 16 + (lane >> 2);
#pragma unroll
        for (int n = 0; n < 4; n++) {
            int col = cv0 + wp * 32 + n * 8 + ((lane & 3) << 1);
            *(float2*)(outp + row * C_ + col) = make_float2(acc[m][n][0], acc[m][n][1]);
            *(float2*)(outp + (row + 8) * C_ + col) = make_float2(acc[m][n][2], acc[m][n][3]);
        }
    }
}

__global__ void __launch_bounds__(64) k_red() {
    int ck = blockIdx.x, b = blockIdx.y, cv4 = threadIdx.x * 4;
    float4 s = make_float4(0.f, 0.f, 0.f, 0.f);
    for (int sp = 0; sp < 16; sp++) {
        float4 v = *(const float4*)(g_kvp + ((size_t)(b * 16 + sp) * C_ + ck) * C_ + cv4);
        s.x += v.x; s.y += v.y; s.z += v.z; s.w += v.w;
    }
    float inv = 1.0f / (g_ksum[b * C_ + ck] + 1e-6f);
    s.x *= inv; s.y *= inv; s.z *= inv; s.w *= inv;
    *(float4*)(g_kvn + (size_t)(b * C_ + ck) * C_ + cv4) = s;
}

// M[b] = Wp @ kvn[b]
__global__ void __launch_bounds__(256, 1) k_m(const float* __restrict__ Wp) {
    extern __shared__ float sm[];
    float* Xs = sm;
    float* Wbuf = sm + 256 * LDX;
    int b = blockIdx.y, d0 = blockIdx.x * 64;
    int tid = threadIdx.x, lane = tid & 31, warp = tid >> 5;
    int wo = warp & 3, wp_ = warp >> 2;
#pragma unroll
    for (int i = 0; i < 16; i++) {
        int lin = i * 256 + tid, c = lin >> 4, d4 = (lin & 15) << 2;
        float4 v = *(const float4*)(g_kvn + (size_t)(b * C_ + c) * C_ + d0 + d4);
        v.x = to_tf32(v.x); v.y = to_tf32(v.y); v.z = to_tf32(v.z); v.w = to_tf32(v.w);
        *(float4*)(Xs + c * LDX + d4) = v;
    }
    float acc[4][4][4];
    gemm_tile(Wp, Xs, Wbuf, tid, lane, wo, wp_, acc);
    float* outp = g_M + (size_t)b * C_ * C_;
#pragma unroll
    for (int m = 0; m < 4; m++) {
        int row = wo * 64 + m * 16 + (lane >> 2);
#pragma unroll
        for (int n = 0; n < 4; n++) {
            int col = d0 + wp_ * 32 + n * 8 + ((lane & 3) << 1);
            *(float2*)(outp + row * C_ + col) = make_float2(acc[m][n][0], acc[m][n][1]);
            *(float2*)(outp + (row + 8) * C_ + col) = make_float2(acc[m][n][2], acc[m][n][3]);
        }
    }
}

// out = M @ q + bp + x
__global__ void __launch_bounds__(256, 1) k_out(const float* __restrict__ x,
                                                const float* __restrict__ bp, float* __restrict__ out) {
    extern __shared__ float sm[];
    float* Xs = sm;
    float* Wbuf = sm + 256 * LDX;
    int b = blockIdx.y, p0 = blockIdx.x * 64;
    int tid = threadIdx.x, lane = tid & 31, warp = tid >> 5;
    int wo = warp & 3, wp = warp >> 2;
#pragma unroll
    for (int i = 0; i < 16; i++) {
        int lin = i * 256 + tid, c = lin >> 4, p4 = (lin & 15) << 2;
        float4 v = *(const float4*)(g_q + ((size_t)(b * C_ + c)) * HW_ + p0 + p4);
        v.x = to_tf32(v.x); v.y = to_tf32(v.y); v.z = to_tf32(v.z); v.w = to_tf32(v.w);
        *(float4*)(Xs + c * LDX + p4) = v;
    }
    float acc[4][4][4];
    gemm_tile(g_M + (size_t)b * C_ * C_, Xs, Wbuf, tid, lane, wo, wp, acc);
#pragma unroll
    for (int m = 0; m < 4; m++) {
        int row = wo * 64 + m * 16 + (lane >> 2);
        float b0 = bp[row], b1 = bp[row + 8];
        size_t o0 = ((size_t)(b * C_ + row)) * HW_ + p0;
        size_t o1 = ((size_t)(b * C_ + row + 8)) * HW_ + p0;
#pragma unroll
        for (int n = 0; n < 4; n++) {
            int col = wp * 32 + n * 8 + ((lane & 3) << 1);
            float2 x0 = *(const float2*)(x + o0 + col);
            float2 x1 = *(const float2*)(x + o1 + col);
            *(float2*)(out + o0 + col) = make_float2(acc[m][n][0] + b0 + x0.x, acc[m][n][1] + b0 + x0.y);
            *(float2*)(out + o1 + col) = make_float2(acc[m][n][2] + b1 + x1.x, acc[m][n][3] + b1 + x1.y);
        }
    }
}

extern "C" void kernel_launch(void* const* d_in, const int* in_sizes, int n_in,
                              void* d_out, int out_size) {
    const float* x = (const float*)d_in[0];
    const float* gamma = (const float*)d_in[1];
    const float* beta = (const float*)d_in[2];
    const float* Wq = (const float*)d_in[3];
    const float* bq = (const float*)d_in[4];
    const float* Wk = (const float*)d_in[5];
    const float* bk = (const float*)d_in[6];
    const float* Wv = (const float*)d_in[7];
    const float* bv = (const float*)d_in[8];
    const float* Wp = (const float*)d_in[9];
    const float* bp = (const float*)d_in[10];
    float* out = (float*)d_out;

    static bool attr_set = false;
    const int SMEM_BIG = 256 * LDX * 4 + 2 * 256 * LDW * 4 + 2 * 256 * 4;
    if (!attr_set) {
        cudaFuncSetAttribute(k_qkv, cudaFuncAttributeMaxDynamicSharedMemorySize, SMEM_BIG);
        cudaFuncSetAttribute(k_m, cudaFuncAttributeMaxDynamicSharedMemorySize, SMEM_BIG);
        cudaFuncSetAttribute(k_out, cudaFuncAttributeMaxDynamicSharedMemorySize, SMEM_BIG);
        attr_set = true;
    }
    k0_zero<<<1, 128>>>();
    k_stats<<<dim3(16, 64), 256>>>(x);
    k_qkv<<<dim3(256, 8), 256, SMEM_BIG>>>(x, gamma, beta, Wq, bq, Wk, bk, Wv, bv);
    k_ksum<<<2048, 128>>>();
    k_kv<<<dim3(64, 8), 256>>>();
    k_red<<<dim3(256, 8), 64>>>();
    k_m<<<dim3(4, 8), 256, SMEM_BIG>>>(Wp);
    k_out<<<dim3(256, 8), 256, SMEM_BIG>>>(x, bp, out);
}

// round 4
// speedup vs baseline: 1.0919x; 1.0919x over previous
#include <cuda_runtime.h>
#include <cstdint>

#define B_   8
#define C_   256
#define HW_  16384
#define NG_  524288.0f
#define LDX  72      // Xs pad: 72 mod 32 = 8 -> B-frag LDS conflict-free
#define LDW  20      // W chunk pad (16-wide chunk): 20 mod 32 -> A-frag conflict-free
#define LDP  36      // k_kv tile pad: 36 mod 32 = 4 -> conflict-free
#define WBUFSZ (256 * LDW)

// scratch (device globals; allocation APIs forbidden)
__device__ float g_q[(size_t)B_ * C_ * HW_];
__device__ float g_k[(size_t)B_ * C_ * HW_];
__device__ float g_v[(size_t)B_ * C_ * HW_];
__device__ float g_kvp[(size_t)B_ * 16 * C_ * C_];
__device__ float g_kvn[B_ * C_ * C_];
__device__ float g_M[B_ * C_ * C_];
__device__ float g_ksum[B_ * C_];
__device__ float g_sum[B_ * 8];
__device__ float g_sq[B_ * 8];
__device__ float g_Wt[4 * 65536];   // tf32-rounded Wq, Wk, Wv, Wp

__device__ __forceinline__ float to_tf32(float x) {
    uint32_t u; asm("cvt.rna.tf32.f32 %0, %1;" : "=r"(u) : "f"(x));
    return __uint_as_float(u);
}
__device__ __forceinline__ float elu1(float x) { return x > 0.f ? x + 1.f : __expf(x); }
__device__ __forceinline__ void mma8(float c[4], const uint32_t a[4], const uint32_t b[2]) {
    asm volatile("mma.sync.aligned.m16n8k8.row.col.f32.tf32.tf32.f32 "
        "{%0,%1,%2,%3},{%4,%5,%6,%7},{%8,%9},{%0,%1,%2,%3};\n"
        : "+f"(c[0]), "+f"(c[1]), "+f"(c[2]), "+f"(c[3])
        : "r"(a[0]), "r"(a[1]), "r"(a[2]), "r"(a[3]), "r"(b[0]), "r"(b[1]));
}
__device__ __forceinline__ void cp16(float* dst, const float* src) {
    uint32_t d = (uint32_t)__cvta_generic_to_shared(dst);
    asm volatile("cp.async.ca.shared.global [%0], [%1], 16;\n" :: "r"(d), "l"(src));
}
#define CP_COMMIT() asm volatile("cp.async.commit_group;\n")
#define CP_WAIT1()  asm volatile("cp.async.wait_group 1;\n")
#define CP_WAIT0()  asm volatile("cp.async.wait_group 0;\n")

// C[256,64] = W[256,256](tf32, global) @ Xs[256,LDX]; warp tile 64x32 (4x2 warps).
// 16 K-chunks of 16, cp.async double-buffered into Wbuf.
__device__ void gemm_tile(const float* __restrict__ Wg, const float* __restrict__ Xs,
                          float* Wbuf, int tid, int lane, int wo, int wp, float acc[4][4][4]) {
#pragma unroll
    for (int m = 0; m < 4; m++)
#pragma unroll
        for (int n = 0; n < 4; n++)
#pragma unroll
            for (int i = 0; i < 4; i++) acc[m][n][i] = 0.f;
#pragma unroll
    for (int i = 0; i < 4; i++) {
        int lin = i * 256 + tid, o = lin >> 2, k4 = (lin & 3) << 2;
        cp16(Wbuf + o * LDW + k4, Wg + o * 256 + k4);
    }
    CP_COMMIT();
    for (int kc = 0; kc < 16; kc++) {
        if (kc < 15) {
            float* Wn = Wbuf + ((kc + 1) & 1) * WBUFSZ;
#pragma unroll
            for (int i = 0; i < 4; i++) {
                int lin = i * 256 + tid, o = lin >> 2, k4 = (lin & 3) << 2;
                cp16(Wn + o * LDW + k4, Wg + o * 256 + (kc + 1) * 16 + k4);
            }
            CP_COMMIT();
            CP_WAIT1();
        } else {
            CP_WAIT0();
        }
        __syncthreads();
        const float* Wc = Wbuf + (kc & 1) * WBUFSZ;
#pragma unroll
        for (int ks = 0; ks < 2; ks++) {
            int kk = ks * 8 + (lane & 3);
            uint32_t a[4][4];
#pragma unroll
            for (int m = 0; m < 4; m++) {
                int row = wo * 64 + m * 16 + (lane >> 2);
                a[m][0] = __float_as_uint(Wc[row * LDW + kk]);
                a[m][1] = __float_as_uint(Wc[(row + 8) * LDW + kk]);
                a[m][2] = __float_as_uint(Wc[row * LDW + kk + 4]);
                a[m][3] = __float_as_uint(Wc[(row + 8) * LDW + kk + 4]);
            }
            uint32_t bf[4][2];
#pragma unroll
            for (int n = 0; n < 4; n++) {
                int col = wp * 32 + n * 8 + (lane >> 2);
                int kg = kc * 16 + ks * 8 + (lane & 3);
                bf[n][0] = __float_as_uint(Xs[kg * LDX + col]);
                bf[n][1] = __float_as_uint(Xs[(kg + 4) * LDX + col]);
            }
#pragma unroll
            for (int m = 0; m < 4; m++)
#pragma unroll
                for (int n = 0; n < 4; n++) mma8(acc[m][n], a[m], bf[n]);
        }
        __syncthreads();
    }
}

__global__ void k0_zero() {
    int i = blockIdx.x * 256 + threadIdx.x;
    if (i < B_ * C_) g_ksum[i] = 0.f;
    if (i < 64) { g_sum[i] = 0.f; g_sq[i] = 0.f; }
}

__global__ void k_prep(const float* __restrict__ Wq, const float* __restrict__ Wk,
                       const float* __restrict__ Wv, const float* __restrict__ Wp) {
    int i = blockIdx.x * 256 + threadIdx.x;
    g_Wt[i] = to_tf32(Wq[i]);
    g_Wt[65536 + i] = to_tf32(Wk[i]);
    g_Wt[131072 + i] = to_tf32(Wv[i]);
    g_Wt[196608 + i] = to_tf32(Wp[i]);
}

__global__ void __launch_bounds__(256) k_stats(const float* __restrict__ x) {
    int bg = blockIdx.y;
    const float* base = x + (size_t)bg * 524288 + blockIdx.x * 32768;
    int tid = threadIdx.x, lane = tid & 31, warp = tid >> 5;
    float s = 0.f, sq = 0.f;
    for (int i = tid; i < 8192; i += 256) {
        float4 v = *(const float4*)(base + i * 4);
        s += v.x + v.y + v.z + v.w;
        sq = fmaf(v.x, v.x, sq); sq = fmaf(v.y, v.y, sq);
        sq = fmaf(v.z, v.z, sq); sq = fmaf(v.w, v.w, sq);
    }
#pragma unroll
    for (int o = 16; o > 0; o >>= 1) {
        s += __shfl_xor_sync(~0u, s, o); sq += __shfl_xor_sync(~0u, sq, o);
    }
    __shared__ float rs[8], rq[8];
    if (lane == 0) { rs[warp] = s; rq[warp] = sq; }
    __syncthreads();
    if (tid == 0) {
        float S = 0.f, Q = 0.f;
#pragma unroll
        for (int i = 0; i < 8; i++) { S += rs[i]; Q += rq[i]; }
        atomicAdd(&g_sum[bg], S); atomicAdd(&g_sq[bg], Q);
    }
}

// fused GN + Q/K/V convs + ksum; writes tf32-rounded g_q (elu+1), g_k (elu+1), g_v
__global__ void __launch_bounds__(256, 2) k_qkv(
    const float* __restrict__ x, const float* __restrict__ gamma, const float* __restrict__ beta,
    const float* __restrict__ bq, const float* __restrict__ bk, const float* __restrict__ bv) {
    extern __shared__ float sm[];
    float* Xs = sm;                       // [256][LDX]
    float* Wbuf = sm + 256 * LDX;         // 2 x [256][LDW]; aliased for sc/tb during X load
    float* sc = Wbuf;
    float* tb = Wbuf + 256;
    int b = blockIdx.y, p0 = blockIdx.x * 64;
    int tid = threadIdx.x, lane = tid & 31, warp = tid >> 5;
    int wo = warp & 3, wp = warp >> 2;
    {
        int c = tid, g = c >> 5;
        float mean = g_sum[b * 8 + g] * (1.0f / NG_);
        float var = g_sq[b * 8 + g] * (1.0f / NG_) - mean * mean;
        float s = rsqrtf(var + 1e-5f) * gamma[c];
        sc[c] = s; tb[c] = beta[c] - mean * s;
    }
    __syncthreads();
#pragma unroll
    for (int i = 0; i < 16; i++) {
        int lin = i * 256 + tid, c = lin >> 4, p4 = (lin & 15) << 2;
        float4 v = *(const float4*)(x + ((size_t)(b * C_ + c)) * HW_ + p0 + p4);
        float s = sc[c], t = tb[c];
        v.x = to_tf32(fmaf(v.x, s, t)); v.y = to_tf32(fmaf(v.y, s, t));
        v.z = to_tf32(fmaf(v.z, s, t)); v.w = to_tf32(fmaf(v.w, s, t));
        *(float4*)(Xs + c * LDX + p4) = v;
    }
    __syncthreads();
    float acc[4][4][4];
    // Q
    gemm_tile(g_Wt, Xs, Wbuf, tid, lane, wo, wp, acc);
#pragma unroll
    for (int m = 0; m < 4; m++) {
        int row = wo * 64 + m * 16 + (lane >> 2);
        float b0 = bq[row], b1 = bq[row + 8];
        size_t o0 = ((size_t)(b * C_ + row)) * HW_ + p0;
        size_t o1 = ((size_t)(b * C_ + row + 8)) * HW_ + p0;
#pragma unroll
        for (int n = 0; n < 4; n++) {
            int col = wp * 32 + n * 8 + ((lane & 3) << 1);
            *(float2*)(g_q + o0 + col) = make_float2(to_tf32(elu1(acc[m][n][0] + b0)), to_tf32(elu1(acc[m][n][1] + b0)));
            *(float2*)(g_q + o1 + col) = make_float2(to_tf32(elu1(acc[m][n][2] + b1)), to_tf32(elu1(acc[m][n][3] + b1)));
        }
    }
    // K (+ fused ksum)
    gemm_tile(g_Wt + 65536, Xs, Wbuf, tid, lane, wo, wp, acc);
#pragma unroll
    for (int m = 0; m < 4; m++) {
        int row = wo * 64 + m * 16 + (lane >> 2);
        float b0 = bk[row], b1 = bk[row + 8];
        size_t o0 = ((size_t)(b * C_ + row)) * HW_ + p0;
        size_t o1 = ((size_t)(b * C_ + row + 8)) * HW_ + p0;
        float s0 = 0.f, s1 = 0.f;
#pragma unroll
        for (int n = 0; n < 4; n++) {
            int col = wp * 32 + n * 8 + ((lane & 3) << 1);
            float e0 = elu1(acc[m][n][0] + b0), e1 = elu1(acc[m][n][1] + b0);
            float e2 = elu1(acc[m][n][2] + b1), e3 = elu1(acc[m][n][3] + b1);
            s0 += e0 + e1; s1 += e2 + e3;
            *(float2*)(g_k + o0 + col) = make_float2(to_tf32(e0), to_tf32(e1));
            *(float2*)(g_k + o1 + col) = make_float2(to_tf32(e2), to_tf32(e3));
        }
        s0 += __shfl_xor_sync(~0u, s0, 1); s0 += __shfl_xor_sync(~0u, s0, 2);
        s1 += __shfl_xor_sync(~0u, s1, 1); s1 += __shfl_xor_sync(~0u, s1, 2);
        if ((lane & 3) == 0) {
            atomicAdd(&g_ksum[b * C_ + row], s0);
            atomicAdd(&g_ksum[b * C_ + row + 8], s1);
        }
    }
    // V
    gemm_tile(g_Wt + 131072, Xs, Wbuf, tid, lane, wo, wp, acc);
#pragma unroll
    for (int m = 0; m < 4; m++) {
        int row = wo * 64 + m * 16 + (lane >> 2);
        float b0 = bv[row], b1 = bv[row + 8];
        size_t o0 = ((size_t)(b * C_ + row)) * HW_ + p0;
        size_t o1 = ((size_t)(b * C_ + row + 8)) * HW_ + p0;
#pragma unroll
        for (int n = 0; n < 4; n++) {
            int col = wp * 32 + n * 8 + ((lane & 3) << 1);
            *(float2*)(g_v + o0 + col) = make_float2(to_tf32(acc[m][n][0] + b0), to_tf32(acc[m][n][1] + b0));
            *(float2*)(g_v + o1 + col) = make_float2(to_tf32(acc[m][n][2] + b1), to_tf32(acc[m][n][3] + b1));
        }
    }
}

// kv split-K with cp.async double-buffered pipeline.
// block(b, s, cvt): kvp[b][s][0:256][cv0:cv0+64] over 1024 pixels in 32 chunks of 32.
__device__ __forceinline__ void kv_issue(float* buf, int b, int cv0, int p0, int tid) {
#pragma unroll
    for (int i = 0; i < 8; i++) {
        int lin = i * 256 + tid, c = lin >> 3, p4 = (lin & 7) << 2;
        cp16(buf + c * LDP + p4, g_k + ((size_t)(b * C_ + c)) * HW_ + p0 + p4);
    }
#pragma unroll
    for (int i = 0; i < 2; i++) {
        int lin = i * 256 + tid, c = lin >> 3, p4 = (lin & 7) << 2;
        cp16(buf + 256 * LDP + c * LDP + p4, g_v + ((size_t)(b * C_ + cv0 + c)) * HW_ + p0 + p4);
    }
    CP_COMMIT();
}

__global__ void __launch_bounds__(256, 2) k_kv() {
    extern __shared__ float sm[];
    const int TSZ = 320 * LDP;
    int s = blockIdx.x >> 2, cvt = blockIdx.x & 3, b = blockIdx.y;
    int cv0 = cvt * 64;
    int tid = threadIdx.x, lane = tid & 31, warp = tid >> 5;
    int wo = warp & 3, wp = warp >> 2;
    float acc[4][4][4];
#pragma unroll
    for (int m = 0; m < 4; m++)
#pragma unroll
        for (int n = 0; n < 4; n++)
#pragma unroll
            for (int i = 0; i < 4; i++) acc[m][n][i] = 0.f;
    kv_issue(sm, b, cv0, s * 1024, tid);
    for (int ch = 0; ch < 32; ch++) {
        if (ch < 31) {
            kv_issue(sm + ((ch + 1) & 1) * TSZ, b, cv0, s * 1024 + (ch + 1) * 32, tid);
            CP_WAIT1();
        } else {
            CP_WAIT0();
        }
        __syncthreads();
        const float* Ks = sm + (ch & 1) * TSZ;
        const float* Vs = Ks + 256 * LDP;
#pragma unroll
        for (int ks = 0; ks < 4; ks++) {
            int kk = ks * 8 + (lane & 3);
            uint32_t a[4][4];
#pragma unroll
            for (int m = 0; m < 4; m++) {
                int row = wo * 64 + m * 16 + (lane >> 2);
                a[m][0] = __float_as_uint(Ks[row * LDP + kk]);
                a[m][1] = __float_as_uint(Ks[(row + 8) * LDP + kk]);
                a[m][2] = __float_as_uint(Ks[row * LDP + kk + 4]);
                a[m][3] = __float_as_uint(Ks[(row + 8) * LDP + kk + 4]);
            }
            uint32_t bf[4][2];
#pragma unroll
            for (int n = 0; n < 4; n++) {
                int col = wp * 32 + n * 8 + (lane >> 2);
                bf[n][0] = __float_as_uint(Vs[col * LDP + kk]);
                bf[n][1] = __float_as_uint(Vs[col * LDP + kk + 4]);
            }
#pragma unroll
            for (int m = 0; m < 4; m++)
#pragma unroll
                for (int n = 0; n < 4; n++) mma8(acc[m][n], a[m], bf[n]);
        }
        __syncthreads();
    }
    float* outp = g_kvp + ((size_t)(b * 16 + s)) * C_ * C_;
#pragma unroll
    for (int m = 0; m < 4; m++) {
        int row = wo * 64 + m * 16 + (lane >> 2);
#pragma unroll
        for (int n = 0; n < 4; n++) {
            int col = cv0 + wp * 32 + n * 8 + ((lane & 3) << 1);
            *(float2*)(outp + row * C_ + col) = make_float2(acc[m][n][0], acc[m][n][1]);
            *(float2*)(outp + (row + 8) * C_ + col) = make_float2(acc[m][n][2], acc[m][n][3]);
        }
    }
}

__global__ void __launch_bounds__(64) k_red() {
    int ck = blockIdx.x, b = blockIdx.y, cv4 = threadIdx.x * 4;
    float4 s = make_float4(0.f, 0.f, 0.f, 0.f);
    for (int sp = 0; sp < 16; sp++) {
        float4 v = *(const float4*)(g_kvp + ((size_t)(b * 16 + sp) * C_ + ck) * C_ + cv4);
        s.x += v.x; s.y += v.y; s.z += v.z; s.w += v.w;
    }
    float inv = 1.0f / (g_ksum[b * C_ + ck] + 1e-6f);
    s.x = to_tf32(s.x * inv); s.y = to_tf32(s.y * inv);
    s.z = to_tf32(s.z * inv); s.w = to_tf32(s.w * inv);
    *(float4*)(g_kvn + (size_t)(b * C_ + ck) * C_ + cv4) = s;
}

// M[b] = Wp @ kvn[b] (tf32-rounded store)
__global__ void __launch_bounds__(256, 2) k_m() {
    extern __shared__ float sm[];
    float* Xs = sm;
    float* Wbuf = sm + 256 * LDX;
    int b = blockIdx.y, d0 = blockIdx.x * 64;
    int tid = threadIdx.x, lane = tid & 31, warp = tid >> 5;
    int wo = warp & 3, wp_ = warp >> 2;
#pragma unroll
    for (int i = 0; i < 16; i++) {
        int lin = i * 256 + tid, c = lin >> 4, d4 = (lin & 15) << 2;
        float4 v = *(const float4*)(g_kvn + (size_t)(b * C_ + c) * C_ + d0 + d4);
        *(float4*)(Xs + c * LDX + d4) = v;
    }
    __syncthreads();
    float acc[4][4][4];
    gemm_tile(g_Wt + 196608, Xs, Wbuf, tid, lane, wo, wp_, acc);
    float* outp = g_M + (size_t)b * C_ * C_;
#pragma unroll
    for (int m = 0; m < 4; m++) {
        int row = wo * 64 + m * 16 + (lane >> 2);
#pragma unroll
        for (int n = 0; n < 4; n++) {
            int col = d0 + wp_ * 32 + n * 8 + ((lane & 3) << 1);
            *(float2*)(outp + row * C_ + col) = make_float2(to_tf32(acc[m][n][0]), to_tf32(acc[m][n][1]));
            *(float2*)(outp + (row + 8) * C_ + col) = make_float2(to_tf32(acc[m][n][2]), to_tf32(acc[m][n][3]));
        }
    }
}

// out = M @ q + bp + x
__global__ void __launch_bounds__(256, 2) k_out(const float* __restrict__ x,
                                                const float* __restrict__ bp, float* __restrict__ out) {
    extern __shared__ float sm[];
    float* Xs = sm;
    float* Wbuf = sm + 256 * LDX;
    int b = blockIdx.y, p0 = blockIdx.x * 64;
    int tid = threadIdx.x, lane = tid & 31, warp = tid >> 5;
    int wo = warp & 3, wp = warp >> 2;
#pragma unroll
    for (int i = 0; i < 16; i++) {
        int lin = i * 256 + tid, c = lin >> 4, p4 = (lin & 15) << 2;
        float4 v = *(const float4*)(g_q + ((size_t)(b * C_ + c)) * HW_ + p0 + p4);
        *(float4*)(Xs + c * LDX + p4) = v;
    }
    __syncthreads();
    float acc[4][4][4];
    gemm_tile(g_M + (size_t)b * C_ * C_, Xs, Wbuf, tid, lane, wo, wp, acc);
#pragma unroll
    for (int m = 0; m < 4; m++) {
        int row = wo * 64 + m * 16 + (lane >> 2);
        float b0 = bp[row], b1 = bp[row + 8];
        size_t o0 = ((size_t)(b * C_ + row)) * HW_ + p0;
        size_t o1 = ((size_t)(b * C_ + row + 8)) * HW_ + p0;
#pragma unroll
        for (int n = 0; n < 4; n++) {
            int col = wp * 32 + n * 8 + ((lane & 3) << 1);
            float2 x0 = *(const float2*)(x + o0 + col);
            float2 x1 = *(const float2*)(x + o1 + col);
            *(float2*)(out + o0 + col) = make_float2(acc[m][n][0] + b0 + x0.x, acc[m][n][1] + b0 + x0.y);
            *(float2*)(out + o1 + col) = make_float2(acc[m][n][2] + b1 + x1.x, acc[m][n][3] + b1 + x1.y);
        }
    }
}

extern "C" void kernel_launch(void* const* d_in, const int* in_sizes, int n_in,
                              void* d_out, int out_size) {
    const float* x = (const float*)d_in[0];
    const float* gamma = (const float*)d_in[1];
    const float* beta = (const float*)d_in[2];
    const float* Wq = (const float*)d_in[3];
    const float* bq = (const float*)d_in[4];
    const float* Wk = (const float*)d_in[5];
    const float* bk = (const float*)d_in[6];
    const float* Wv = (const float*)d_in[7];
    const float* bv = (const float*)d_in[8];
    const float* Wp = (const float*)d_in[9];
    const float* bp = (const float*)d_in[10];
    float* out = (float*)d_out;

    const int SMEM_GEMM = (256 * LDX + 2 * WBUFSZ) * 4;   // 114688 B -> 2 CTAs/SM
    const int SMEM_KV = 2 * 320 * LDP * 4;                 // 92160 B  -> 2 CTAs/SM
    cudaFuncSetAttribute(k_qkv, cudaFuncAttributeMaxDynamicSharedMemorySize, SMEM_GEMM);
    cudaFuncSetAttribute(k_m, cudaFuncAttributeMaxDynamicSharedMemorySize, SMEM_GEMM);
    cudaFuncSetAttribute(k_out, cudaFuncAttributeMaxDynamicSharedMemorySize, SMEM_GEMM);
    cudaFuncSetAttribute(k_kv, cudaFuncAttributeMaxDynamicSharedMemorySize, SMEM_KV);

    k0_zero<<<8, 256>>>();
    k_prep<<<256, 256>>>(Wq, Wk, Wv, Wp);
    k_stats<<<dim3(16, 64), 256>>>(x);
    k_qkv<<<dim3(256, 8), 256, SMEM_GEMM>>>(x, gamma, beta, bq, bk, bv);
    k_kv<<<dim3(64, 8), 256, SMEM_KV>>>();
    k_red<<<dim3(256, 8), 64>>>();
    k_m<<<dim3(4, 8), 256, SMEM_GEMM>>>();
    k_out<<<dim3(256, 8), 256, SMEM_GEMM>>>(x, bp, out);
}

// round 6
// speedup vs baseline: 1.2192x; 1.1166x over previous
#include <cuda_runtime.h>
#include <cstdint>

#define B_   8
#define C_   256
#define HW_  16384
#define NG_  524288.0f

// scratch (device globals; allocation APIs forbidden)
__device__ float g_q[(size_t)B_ * C_ * HW_];
__device__ float g_k[(size_t)B_ * C_ * HW_];   // pixel dim pack8-permuted
__device__ float g_v[(size_t)B_ * C_ * HW_];   // pixel dim pack8-permuted
__device__ float g_kvp[(size_t)B_ * 16 * C_ * C_];
__device__ float g_kvn[B_ * C_ * C_];
__device__ float g_M[B_ * C_ * C_];            // packed-W layout per batch
__device__ float g_ksum[B_ * C_];
__device__ float g_sum[B_ * 8];
__device__ float g_sq[B_ * 8];
__device__ float g_Wt[4 * 65536];              // packed: [mat][kc=16][row=256][16]

__device__ __forceinline__ float to_tf32(float x) {
    uint32_t u; asm("cvt.rna.tf32.f32 %0, %1;" : "=r"(u) : "f"(x));
    return __uint_as_float(u);
}
__device__ __forceinline__ float elu1(float x) { return x > 0.f ? x + 1.f : __expf(x); }
__device__ __forceinline__ int pk8(int i) {     // pack (i, i+4) adjacent within 8-groups
    return (i & ~7) | ((i & 3) << 1) | ((i >> 2) & 1);
}
__device__ __forceinline__ void mma8(float c[4], const uint32_t a[4], const uint32_t b[2]) {
    asm volatile("mma.sync.aligned.m16n8k8.row.col.f32.tf32.tf32.f32 "
        "{%0,%1,%2,%3},{%4,%5,%6,%7},{%8,%9},{%0,%1,%2,%3};\n"
        : "+f"(c[0]), "+f"(c[1]), "+f"(c[2]), "+f"(c[3])
        : "r"(a[0]), "r"(a[1]), "r"(a[2]), "r"(a[3]), "r"(b[0]), "r"(b[1]));
}
__device__ __forceinline__ void cp16(float* dst, const float* src) {
    uint32_t d = (uint32_t)__cvta_generic_to_shared(dst);
    asm volatile("cp.async.ca.shared.global [%0], [%1], 16;\n" :: "r"(d), "l"(src));
}
#define CP_COMMIT() asm volatile("cp.async.commit_group;\n")
#define CP_WAIT1()  asm volatile("cp.async.wait_group 1;\n")
#define CP_WAIT0()  asm volatile("cp.async.wait_group 0;\n")

// C[256,64] = W(packed global) @ Xt[64][256 packed, swizzled]; warp tile 64x32.
// 16 K-chunks of 16, cp.async double-buffered. All frag loads LDS.64, conflict-free.
__device__ __forceinline__ void gemm_tile(const float* __restrict__ Wg, const float* __restrict__ Xt,
                                          float* Wbuf, int tid, int lane, int wo, int wp,
                                          float acc[4][4][4]) {
    int c2 = lane & 3, r = lane >> 2;
#pragma unroll
    for (int m = 0; m < 4; m++)
#pragma unroll
        for (int n = 0; n < 4; n++)
#pragma unroll
            for (int i = 0; i < 4; i++) acc[m][n][i] = 0.f;
    // stage chunk 0
#pragma unroll
    for (int i = 0; i < 4; i++) {
        int lin = i * 256 + tid, row = lin >> 2, fc = lin & 3;
        cp16(Wbuf + row * 16 + ((fc ^ (row & 2)) << 2), Wg + row * 16 + fc * 4);
    }
    CP_COMMIT();
    for (int kc = 0; kc < 16; kc++) {
        if (kc < 15) {
            float* Wn = Wbuf + ((kc + 1) & 1) * 4096;
            const float* src = Wg + (kc + 1) * 4096;
#pragma unroll
            for (int i = 0; i < 4; i++) {
                int lin = i * 256 + tid, row = lin >> 2, fc = lin & 3;
                cp16(Wn + row * 16 + ((fc ^ (row & 2)) << 2), src + row * 16 + fc * 4);
            }
            CP_COMMIT();
            CP_WAIT1();
        } else {
            CP_WAIT0();
        }
        __syncthreads();
        const float* Wc = Wbuf + (kc & 1) * 4096;
#pragma unroll
        for (int ks = 0; ks < 2; ks++) {
            int u = ks * 4 + c2;
            uint32_t a[4][4];
#pragma unroll
            for (int m = 0; m < 4; m++) {
                int row = wo * 64 + m * 16 + r;
                int off = (u ^ ((row & 2) << 1)) << 1;
                float2 x0 = *(const float2*)(Wc + row * 16 + off);
                float2 x1 = *(const float2*)(Wc + (row + 8) * 16 + off);
                a[m][0] = __float_as_uint(x0.x); a[m][1] = __float_as_uint(x1.x);
                a[m][2] = __float_as_uint(x0.y); a[m][3] = __float_as_uint(x1.y);
            }
            int ub = kc * 8 + ks * 4 + c2;
            uint32_t bf[4][2];
#pragma unroll
            for (int n = 0; n < 4; n++) {
                int col = wp * 32 + n * 8 + r;
                float2 bb = *(const float2*)(Xt + col * 256 + ((ub ^ ((col & 3) << 2)) << 1));
                bf[n][0] = __float_as_uint(bb.x); bf[n][1] = __float_as_uint(bb.y);
            }
#pragma unroll
            for (int m = 0; m < 4; m++)
#pragma unroll
                for (int n = 0; n < 4; n++) mma8(acc[m][n], a[m], bf[n]);
        }
        __syncthreads();
    }
}

__global__ void k0_zero() {
    int i = blockIdx.x * 256 + threadIdx.x;
    if (i < B_ * C_) g_ksum[i] = 0.f;
    if (i < 64) { g_sum[i] = 0.f; g_sq[i] = 0.f; }
}

// pack W: [mat][kc=c>>4][row][16] with pk8 within 16
__global__ void k_prep(const float* __restrict__ Wq, const float* __restrict__ Wk,
                       const float* __restrict__ Wv, const float* __restrict__ Wp) {
    int i = blockIdx.x * 256 + threadIdx.x;
    int o = i >> 8, c = i & 255;
    int dst = (c >> 4) * 4096 + o * 16 + pk8(c & 15);
    g_Wt[dst] = to_tf32(Wq[i]);
    g_Wt[65536 + dst] = to_tf32(Wk[i]);
    g_Wt[131072 + dst] = to_tf32(Wv[i]);
    g_Wt[196608 + dst] = to_tf32(Wp[i]);
}

__global__ void __launch_bounds__(256) k_stats(const float* __restrict__ x) {
    int bg = blockIdx.y;
    const float* base = x + (size_t)bg * 524288 + blockIdx.x * 32768;
    int tid = threadIdx.x, lane = tid & 31, warp = tid >> 5;
    float s = 0.f, sq = 0.f;
    for (int i = tid; i < 8192; i += 256) {
        float4 v = *(const float4*)(base + i * 4);
        s += v.x + v.y + v.z + v.w;
        sq = fmaf(v.x, v.x, sq); sq = fmaf(v.y, v.y, sq);
        sq = fmaf(v.z, v.z, sq); sq = fmaf(v.w, v.w, sq);
    }
#pragma unroll
    for (int o = 16; o > 0; o >>= 1) {
        s += __shfl_xor_sync(~0u, s, o); sq += __shfl_xor_sync(~0u, sq, o);
    }
    __shared__ float rs[8], rq[8];
    if (lane == 0) { rs[warp] = s; rq[warp] = sq; }
    __syncthreads();
    if (tid == 0) {
        float S = 0.f, Q = 0.f;
#pragma unroll
        for (int i = 0; i < 8; i++) { S += rs[i]; Q += rq[i]; }
        atomicAdd(&g_sum[bg], S); atomicAdd(&g_sq[bg], Q);
    }
}

// fused GN + Q/K/V convs + ksum. g_q true pixel order; g_k/g_v pixel pk8-permuted.
// sc/tb live in DEDICATED smem (R5 bug: they aliased Wbuf and raced with cp.async W staging).
__global__ void __launch_bounds__(256, 2) k_qkv(
    const float* __restrict__ x, const float* __restrict__ gamma, const float* __restrict__ beta,
    const float* __restrict__ bq, const float* __restrict__ bk, const float* __restrict__ bv) {
    extern __shared__ float sm[];
    float* Xt = sm;                      // [64 cols][256 k] swizzled, 65536B
    float* Wbuf = sm + 64 * 256;         // 2 x 4096 floats
    float* sc = sm + 64 * 256 + 2 * 4096; // dedicated 256
    float* tb = sc + 256;                 // dedicated 256
    int b = blockIdx.y, p0 = blockIdx.x * 64;
    int tid = threadIdx.x, lane = tid & 31, warp = tid >> 5;
    int wo = warp & 3, wp = warp >> 2, c2 = lane & 3;
    {
        int c = tid, g = c >> 5;
        float mean = g_sum[b * 8 + g] * (1.0f / NG_);
        float var = g_sq[b * 8 + g] * (1.0f / NG_) - mean * mean;
        float s = rsqrtf(var + 1e-5f) * gamma[c];
        sc[c] = s; tb[c] = beta[c] - mean * s;
    }
    __syncthreads();
#pragma unroll
    for (int i = 0; i < 16; i++) {
        int lin = i * 256 + tid, c = lin >> 4, p4 = (lin & 15) << 2;
        float4 v = *(const float4*)(x + ((size_t)(b * C_ + c)) * HW_ + p0 + p4);
        float s = sc[c], t = tb[c];
        float vv[4];
        vv[0] = to_tf32(fmaf(v.x, s, t)); vv[1] = to_tf32(fmaf(v.y, s, t));
        vv[2] = to_tf32(fmaf(v.z, s, t)); vv[3] = to_tf32(fmaf(v.w, s, t));
        int u = ((c >> 3) << 2) + (c & 3), sub = (c >> 2) & 1;
#pragma unroll
        for (int j = 0; j < 4; j++) {
            int jj = (j + lane) & 3;
            int col = p4 + jj;
            Xt[col * 256 + ((u ^ (jj << 2)) << 1) + sub] = vv[jj];
        }
    }
    __syncthreads();
    float acc[4][4][4];
    // ---- Q (true pixel layout) ----
    gemm_tile(g_Wt, Xt, Wbuf, tid, lane, wo, wp, acc);
#pragma unroll
    for (int m = 0; m < 4; m++) {
        int row = wo * 64 + m * 16 + (lane >> 2);
        float b0 = bq[row], b1 = bq[row + 8];
        size_t o0 = ((size_t)(b * C_ + row)) * HW_ + p0;
        size_t o1 = ((size_t)(b * C_ + row + 8)) * HW_ + p0;
#pragma unroll
        for (int n = 0; n < 4; n++) {
            int col = wp * 32 + n * 8 + (c2 << 1);
            *(float2*)(g_q + o0 + col) = make_float2(to_tf32(elu1(acc[m][n][0] + b0)), to_tf32(elu1(acc[m][n][1] + b0)));
            *(float2*)(g_q + o1 + col) = make_float2(to_tf32(elu1(acc[m][n][2] + b1)), to_tf32(elu1(acc[m][n][3] + b1)));
        }
    }
    // ---- K (pk8 pixel layout) + fused ksum ----
    gemm_tile(g_Wt + 65536, Xt, Wbuf, tid, lane, wo, wp, acc);
#pragma unroll
    for (int m = 0; m < 4; m++) {
        int row = wo * 64 + m * 16 + (lane >> 2);
        float b0 = bk[row], b1 = bk[row + 8];
        size_t o0 = ((size_t)(b * C_ + row)) * HW_ + p0;
        size_t o1 = ((size_t)(b * C_ + row + 8)) * HW_ + p0;
        float s0 = 0.f, s1 = 0.f;
#pragma unroll
        for (int n = 0; n < 4; n++) {
            int col = wp * 32 + n * 8 + (c2 << 1);
            int q0 = pk8(col);
            float e0 = elu1(acc[m][n][0] + b0), e1 = elu1(acc[m][n][1] + b0);
            float e2 = elu1(acc[m][n][2] + b1), e3 = elu1(acc[m][n][3] + b1);
            s0 += e0 + e1; s1 += e2 + e3;
            g_k[o0 + q0] = to_tf32(e0); g_k[o0 + q0 + 2] = to_tf32(e1);
            g_k[o1 + q0] = to_tf32(e2); g_k[o1 + q0 + 2] = to_tf32(e3);
        }
        s0 += __shfl_xor_sync(~0u, s0, 1); s0 += __shfl_xor_sync(~0u, s0, 2);
        s1 += __shfl_xor_sync(~0u, s1, 1); s1 += __shfl_xor_sync(~0u, s1, 2);
        if (c2 == 0) {
            atomicAdd(&g_ksum[b * C_ + row], s0);
            atomicAdd(&g_ksum[b * C_ + row + 8], s1);
        }
    }
    // ---- V (pk8 pixel layout) ----
    gemm_tile(g_Wt + 131072, Xt, Wbuf, tid, lane, wo, wp, acc);
#pragma unroll
    for (int m = 0; m < 4; m++) {
        int row = wo * 64 + m * 16 + (lane >> 2);
        float b0 = bv[row], b1 = bv[row + 8];
        size_t o0 = ((size_t)(b * C_ + row)) * HW_ + p0;
        size_t o1 = ((size_t)(b * C_ + row + 8)) * HW_ + p0;
#pragma unroll
        for (int n = 0; n < 4; n++) {
            int col = wp * 32 + n * 8 + (c2 << 1);
            int q0 = pk8(col);
            g_v[o0 + q0] = to_tf32(acc[m][n][0] + b0); g_v[o0 + q0 + 2] = to_tf32(acc[m][n][1] + b0);
            g_v[o1 + q0] = to_tf32(acc[m][n][2] + b1); g_v[o1 + q0 + 2] = to_tf32(acc[m][n][3] + b1);
        }
    }
}

// kv split-K, cp.async double-buffered, swizzled stride-32 rows (no pad).
__device__ __forceinline__ void kv_issue(float* buf, int b, int cv0, int p0, int tid) {
#pragma unroll
    for (int i = 0; i < 8; i++) {
        int lin = i * 256 + tid, row = lin >> 3, fc = lin & 7;
        cp16(buf + row * 32 + ((fc ^ ((row & 3) << 1)) << 2),
             g_k + ((size_t)(b * C_ + row)) * HW_ + p0 + fc * 4);
    }
#pragma unroll
    for (int i = 0; i < 2; i++) {
        int lin = i * 256 + tid, row = lin >> 3, fc = lin & 7;
        cp16(buf + 8192 + row * 32 + ((fc ^ ((row & 3) << 1)) << 2),
             g_v + ((size_t)(b * C_ + cv0 + row)) * HW_ + p0 + fc * 4);
    }
    CP_COMMIT();
}

__global__ void __launch_bounds__(256, 2) k_kv() {
    extern __shared__ float sm[];
    const int TSZ = 8192 + 2048;
    int s = blockIdx.x >> 2, cvt = blockIdx.x & 3, b = blockIdx.y;
    int cv0 = cvt * 64;
    int tid = threadIdx.x, lane = tid & 31, warp = tid >> 5;
    int wo = warp & 3, wp = warp >> 2, c2 = lane & 3, r = lane >> 2;
    float acc[4][4][4];
#pragma unroll
    for (int m = 0; m < 4; m++)
#pragma unroll
        for (int n = 0; n < 4; n++)
#pragma unroll
            for (int i = 0; i < 4; i++) acc[m][n][i] = 0.f;
    kv_issue(sm, b, cv0, s * 1024, tid);
    for (int ch = 0; ch < 32; ch++) {
        if (ch < 31) {
            kv_issue(sm + ((ch + 1) & 1) * TSZ, b, cv0, s * 1024 + (ch + 1) * 32, tid);
            CP_WAIT1();
        } else {
            CP_WAIT0();
        }
        __syncthreads();
        const float* Ks = sm + (ch & 1) * TSZ;
        const float* Vs = Ks + 8192;
#pragma unroll
        for (int ks = 0; ks < 4; ks++) {
            int u = ks * 4 + c2;
            uint32_t a[4][4];
#pragma unroll
            for (int m = 0; m < 4; m++) {
                int row = wo * 64 + m * 16 + r;
                int off = (u ^ ((row & 3) << 2)) << 1;
                float2 x0 = *(const float2*)(Ks + row * 32 + off);
                float2 x1 = *(const float2*)(Ks + (row + 8) * 32 + off);
                a[m][0] = __float_as_uint(x0.x); a[m][1] = __float_as_uint(x1.x);
                a[m][2] = __float_as_uint(x0.y); a[m][3] = __float_as_uint(x1.y);
            }
            uint32_t bf[4][2];
#pragma unroll
            for (int n = 0; n < 4; n++) {
                int col = wp * 32 + n * 8 + r;
                float2 bb = *(const float2*)(Vs + col * 32 + ((u ^ ((col & 3) << 2)) << 1));
                bf[n][0] = __float_as_uint(bb.x); bf[n][1] = __float_as_uint(bb.y);
            }
#pragma unroll
            for (int m = 0; m < 4; m++)
#pragma unroll
                for (int n = 0; n < 4; n++) mma8(acc[m][n], a[m], bf[n]);
        }
        __syncthreads();
    }
    float* outp = g_kvp + ((size_t)(b * 16 + s)) * C_ * C_;
#pragma unroll
    for (int m = 0; m < 4; m++) {
        int row = wo * 64 + m * 16 + (lane >> 2);
#pragma unroll
        for (int n = 0; n < 4; n++) {
            int col = cv0 + wp * 32 + n * 8 + (c2 << 1);
            *(float2*)(outp + row * C_ + col) = make_float2(acc[m][n][0], acc[m][n][1]);
            *(float2*)(outp + (row + 8) * C_ + col) = make_float2(acc[m][n][2], acc[m][n][3]);
        }
    }
}

__global__ void __launch_bounds__(64) k_red() {
    int ck = blockIdx.x, b = blockIdx.y, cv4 = threadIdx.x * 4;
    float4 s = make_float4(0.f, 0.f, 0.f, 0.f);
    for (int sp = 0; sp < 16; sp++) {
        float4 v = *(const float4*)(g_kvp + ((size_t)(b * 16 + sp) * C_ + ck) * C_ + cv4);
        s.x += v.x; s.y += v.y; s.z += v.z; s.w += v.w;
    }
    float inv = 1.0f / (g_ksum[b * C_ + ck] + 1e-6f);
    s.x = to_tf32(s.x * inv); s.y = to_tf32(s.y * inv);
    s.z = to_tf32(s.z * inv); s.w = to_tf32(s.w * inv);
    *(float4*)(g_kvn + (size_t)(b * C_ + ck) * C_ + cv4) = s;
}

// M[b] = Wp @ kvn[b]; stored in packed-W layout (k-dim = d)
__global__ void __launch_bounds__(256, 2) k_m() {
    extern __shared__ float sm[];
    float* Xt = sm;
    float* Wbuf = sm + 64 * 256;
    int b = blockIdx.y, d0 = blockIdx.x * 64;
    int tid = threadIdx.x, lane = tid & 31, warp = tid >> 5;
    int wo = warp & 3, wp_ = warp >> 2, c2 = lane & 3;
#pragma unroll
    for (int i = 0; i < 16; i++) {
        int lin = i * 256 + tid, c = lin >> 4, d4 = (lin & 15) << 2;
        float4 v = *(const float4*)(g_kvn + (size_t)(b * C_ + c) * C_ + d0 + d4);
        float vv[4] = {v.x, v.y, v.z, v.w};
        int u = ((c >> 3) << 2) + (c & 3), sub = (c >> 2) & 1;
#pragma unroll
        for (int j = 0; j < 4; j++) {
            int jj = (j + lane) & 3;
            int col = d4 + jj;
            Xt[col * 256 + ((u ^ (jj << 2)) << 1) + sub] = vv[jj];
        }
    }
    __syncthreads();
    float acc[4][4][4];
    gemm_tile(g_Wt + 196608, Xt, Wbuf, tid, lane, wo, wp_, acc);
    float* outp = g_M + (size_t)b * 65536;
#pragma unroll
    for (int m = 0; m < 4; m++) {
        int row = wo * 64 + m * 16 + (lane >> 2);
#pragma unroll
        for (int n = 0; n < 4; n++) {
            int col = d0 + wp_ * 32 + n * 8 + (c2 << 1);
            int kc = col >> 4;
            int pp0 = pk8(col & 15), pp1 = pk8((col + 1) & 15);
            outp[kc * 4096 + row * 16 + pp0] = to_tf32(acc[m][n][0]);
            outp[kc * 4096 + row * 16 + pp1] = to_tf32(acc[m][n][1]);
            outp[kc * 4096 + (row + 8) * 16 + pp0] = to_tf32(acc[m][n][2]);
            outp[kc * 4096 + (row + 8) * 16 + pp1] = to_tf32(acc[m][n][3]);
        }
    }
}

// out = M @ q + bp + x
__global__ void __launch_bounds__(256, 2) k_out(const float* __restrict__ x,
                                                const float* __restrict__ bp, float* __restrict__ out) {
    extern __shared__ float sm[];
    float* Xt = sm;
    float* Wbuf = sm + 64 * 256;
    int b = blockIdx.y, p0 = blockIdx.x * 64;
    int tid = threadIdx.x, lane = tid & 31, warp = tid >> 5;
    int wo = warp & 3, wp = warp >> 2, c2 = lane & 3;
#pragma unroll
    for (int i = 0; i < 16; i++) {
        int lin = i * 256 + tid, d = lin >> 4, p4 = (lin & 15) << 2;
        float4 v = *(const float4*)(g_q + ((size_t)(b * C_ + d)) * HW_ + p0 + p4);
        float vv[4] = {v.x, v.y, v.z, v.w};
        int u = ((d >> 3) << 2) + (d & 3), sub = (d >> 2) & 1;
#pragma unroll
        for (int j = 0; j < 4; j++) {
            int jj = (j + lane) & 3;
            int col = p4 + jj;
            Xt[col * 256 + ((u ^ (jj << 2)) << 1) + sub] = vv[jj];
        }
    }
    __syncthreads();
    float acc[4][4][4];
    gemm_tile(g_M + (size_t)b * 65536, Xt, Wbuf, tid, lane, wo, wp, acc);
#pragma unroll
    for (int m = 0; m < 4; m++) {
        int row = wo * 64 + m * 16 + (lane >> 2);
        float b0 = bp[row], b1 = bp[row + 8];
        size_t o0 = ((size_t)(b * C_ + row)) * HW_ + p0;
        size_t o1 = ((size_t)(b * C_ + row + 8)) * HW_ + p0;
#pragma unroll
        for (int n = 0; n < 4; n++) {
            int col = wp * 32 + n * 8 + (c2 << 1);
            float2 x0 = *(const float2*)(x + o0 + col);
            float2 x1 = *(const float2*)(x + o1 + col);
            *(float2*)(out + o0 + col) = make_float2(acc[m][n][0] + b0 + x0.x, acc[m][n][1] + b0 + x0.y);
            *(float2*)(out + o1 + col) = make_float2(acc[m][n][2] + b1 + x1.x, acc[m][n][3] + b1 + x1.y);
        }
    }
}

extern "C" void kernel_launch(void* const* d_in, const int* in_sizes, int n_in,
                              void* d_out, int out_size) {
    const float* x = (const float*)d_in[0];
    const float* gamma = (const float*)d_in[1];
    const float* beta = (const float*)d_in[2];
    const float* Wq = (const float*)d_in[3];
    const float* bq = (const float*)d_in[4];
    const float* Wk = (const float*)d_in[5];
    const float* bk = (const float*)d_in[6];
    const float* Wv = (const float*)d_in[7];
    const float* bv = (const float*)d_in[8];
    const float* Wp = (const float*)d_in[9];
    const float* bp = (const float*)d_in[10];
    float* out = (float*)d_out;

    const int SMEM_QKV = (64 * 256 + 2 * 4096 + 512) * 4;  // 100352 B -> 2 CTAs/SM
    const int SMEM_GEMM = (64 * 256 + 2 * 4096) * 4;       // 98304 B  -> 2 CTAs/SM
    const int SMEM_KV = 2 * (8192 + 2048) * 4;              // 81920 B  -> 2 CTAs/SM
    cudaFuncSetAttribute(k_qkv, cudaFuncAttributeMaxDynamicSharedMemorySize, SMEM_QKV);
    cudaFuncSetAttribute(k_m, cudaFuncAttributeMaxDynamicSharedMemorySize, SMEM_GEMM);
    cudaFuncSetAttribute(k_out, cudaFuncAttributeMaxDynamicSharedMemorySize, SMEM_GEMM);
    cudaFuncSetAttribute(k_kv, cudaFuncAttributeMaxDynamicSharedMemorySize, SMEM_KV);

    k0_zero<<<8, 256>>>();
    k_prep<<<256, 256>>>(Wq, Wk, Wv, Wp);
    k_stats<<<dim3(16, 64), 256>>>(x);
    k_qkv<<<dim3(256, 8), 256, SMEM_QKV>>>(x, gamma, beta, bq, bk, bv);
    k_kv<<<dim3(64, 8), 256, SMEM_KV>>>();
    k_red<<<dim3(256, 8), 64>>>();
    k_m<<<dim3(4, 8), 256, SMEM_GEMM>>>();
    k_out<<<dim3(256, 8), 256, SMEM_GEMM>>>(x, bp, out);
}

// round 7
// speedup vs baseline: 2.1247x; 1.7427x over previous
#include <cuda_runtime.h>
#include <cuda_fp16.h>
#include <cstdint>

#define B_   8
#define C_   256
#define HW_  16384
#define NG_  524288.0f
#define LDXS 72      // Xs row pad (halves): 72*2/4=36 words, mod 32 = 4 -> ldmatrix conflict-free
#define LDWS 40      // W chunk row pad (halves): 20 words, mod 32 = 20 -> conflict-free

// scratch (device globals; allocation APIs forbidden)
__device__ __half g_q[(size_t)B_ * C_ * HW_];
__device__ __half g_k[(size_t)B_ * C_ * HW_];
__device__ __half g_v[(size_t)B_ * C_ * HW_];
__device__ float  g_kvp[(size_t)B_ * 16 * C_ * C_];
__device__ float  g_kvn[B_ * C_ * C_];
__device__ __half g_M[B_ * C_ * C_];
__device__ float  g_ksum[B_ * C_];
__device__ float  g_sum[B_ * 8];
__device__ float  g_sq[B_ * 8];
__device__ __half g_Wh[4 * 65536];   // fp16 Wq, Wk, Wv, Wp (row-major [o][c])

__device__ __forceinline__ float elu1(float x) { return x > 0.f ? x + 1.f : __expf(x); }

__device__ __forceinline__ void mma16(float c[4], const uint32_t a[4], const uint32_t b0, const uint32_t b1) {
    asm volatile("mma.sync.aligned.m16n8k16.row.col.f32.f16.f16.f32 "
        "{%0,%1,%2,%3},{%4,%5,%6,%7},{%8,%9},{%0,%1,%2,%3};\n"
        : "+f"(c[0]), "+f"(c[1]), "+f"(c[2]), "+f"(c[3])
        : "r"(a[0]), "r"(a[1]), "r"(a[2]), "r"(a[3]), "r"(b0), "r"(b1));
}
__device__ __forceinline__ void ldsm4(uint32_t r[4], uint32_t addr) {
    asm volatile("ldmatrix.sync.aligned.m8n8.x4.shared.b16 {%0,%1,%2,%3}, [%4];"
        : "=r"(r[0]), "=r"(r[1]), "=r"(r[2]), "=r"(r[3]) : "r"(addr));
}
__device__ __forceinline__ void ldsm4t(uint32_t r[4], uint32_t addr) {
    asm volatile("ldmatrix.sync.aligned.m8n8.x4.trans.shared.b16 {%0,%1,%2,%3}, [%4];"
        : "=r"(r[0]), "=r"(r[1]), "=r"(r[2]), "=r"(r[3]) : "r"(addr));
}
__device__ __forceinline__ void cp16(void* dst, const void* src) {
    uint32_t d = (uint32_t)__cvta_generic_to_shared(dst);
    asm volatile("cp.async.ca.shared.global [%0], [%1], 16;\n" :: "r"(d), "l"(src));
}
#define CP_COMMIT() asm volatile("cp.async.commit_group;\n")
#define CP_WAIT1()  asm volatile("cp.async.wait_group 1;\n")
#define CP_WAIT0()  asm volatile("cp.async.wait_group 0;\n")

// C[256,64] = W[256,256](half,row-major global) @ Xs[k=256][n=64] (smem half, LDXS pad).
// 8 K-chunks of 32, cp.async double-buffered. A: ldmatrix.x4; B: ldmatrix.x4.trans.
__device__ __forceinline__ void gemm_h(const __half* __restrict__ Wg, uint32_t xs,
                                       __half* Wbuf, int tid, int lane, int wo, int wp,
                                       float acc[4][4][4]) {
#pragma unroll
    for (int m = 0; m < 4; m++)
#pragma unroll
        for (int n = 0; n < 4; n++)
#pragma unroll
            for (int i = 0; i < 4; i++) acc[m][n][i] = 0.f;
    uint32_t wb = (uint32_t)__cvta_generic_to_shared(Wbuf);
    int rowA = lane & 15;                 // + wo*64 + m*16
    int colA = (lane & 16) >> 1;          // halves
    int rowB = (lane & 7) + (lane & 8);   // + k0
    int colB = (lane & 16) >> 1;          // + wp*32 + t*16
#pragma unroll
    for (int i = 0; i < 4; i++) {
        int lin = i * 256 + tid, row = lin >> 2, seg = lin & 3;
        cp16(Wbuf + row * LDWS + seg * 8, Wg + row * 256 + seg * 8);
    }
    CP_COMMIT();
    for (int kc = 0; kc < 8; kc++) {
        if (kc < 7) {
            __half* Wn = Wbuf + ((kc + 1) & 1) * (256 * LDWS);
            const __half* src = Wg + (kc + 1) * 32;
#pragma unroll
            for (int i = 0; i < 4; i++) {
                int lin = i * 256 + tid, row = lin >> 2, seg = lin & 3;
                cp16(Wn + row * LDWS + seg * 8, src + row * 256 + seg * 8);
            }
            CP_COMMIT();
            CP_WAIT1();
        } else {
            CP_WAIT0();
        }
        __syncthreads();
        uint32_t wcb = wb + ((kc & 1) * (256 * LDWS)) * 2;
#pragma unroll
        for (int ks = 0; ks < 2; ks++) {
            uint32_t A[4][4];
#pragma unroll
            for (int m = 0; m < 4; m++)
                ldsm4(A[m], wcb + ((wo * 64 + m * 16 + rowA) * LDWS + ks * 16 + colA) * 2);
            uint32_t Bv[2][4];
            int kg = kc * 32 + ks * 16;
#pragma unroll
            for (int t = 0; t < 2; t++)
                ldsm4t(Bv[t], xs + ((kg + rowB) * LDXS + wp * 32 + t * 16 + colB) * 2);
#pragma unroll
            for (int m = 0; m < 4; m++)
#pragma unroll
                for (int n = 0; n < 4; n++)
                    mma16(acc[m][n], A[m], Bv[n >> 1][(n & 1) * 2], Bv[n >> 1][(n & 1) * 2 + 1]);
        }
        __syncthreads();
    }
}

__global__ void k0_zero() {
    int i = blockIdx.x * 256 + threadIdx.x;
    if (i < B_ * C_) g_ksum[i] = 0.f;
    if (i < 64) { g_sum[i] = 0.f; g_sq[i] = 0.f; }
}

__global__ void k_prep(const float* __restrict__ Wq, const float* __restrict__ Wk,
                       const float* __restrict__ Wv, const float* __restrict__ Wp) {
    int i = blockIdx.x * 256 + threadIdx.x;
    g_Wh[i] = __float2half_rn(Wq[i]);
    g_Wh[65536 + i] = __float2half_rn(Wk[i]);
    g_Wh[131072 + i] = __float2half_rn(Wv[i]);
    g_Wh[196608 + i] = __float2half_rn(Wp[i]);
}

__global__ void __launch_bounds__(256) k_stats(const float* __restrict__ x) {
    int bg = blockIdx.y;
    const float* base = x + (size_t)bg * 524288 + blockIdx.x * 32768;
    int tid = threadIdx.x, lane = tid & 31, warp = tid >> 5;
    float s = 0.f, sq = 0.f;
    for (int i = tid; i < 8192; i += 256) {
        float4 v = *(const float4*)(base + i * 4);
        s += v.x + v.y + v.z + v.w;
        sq = fmaf(v.x, v.x, sq); sq = fmaf(v.y, v.y, sq);
        sq = fmaf(v.z, v.z, sq); sq = fmaf(v.w, v.w, sq);
    }
#pragma unroll
    for (int o = 16; o > 0; o >>= 1) {
        s += __shfl_xor_sync(~0u, s, o); sq += __shfl_xor_sync(~0u, sq, o);
    }
    __shared__ float rs[8], rq[8];
    if (lane == 0) { rs[warp] = s; rq[warp] = sq; }
    __syncthreads();
    if (tid == 0) {
        float S = 0.f, Q = 0.f;
#pragma unroll
        for (int i = 0; i < 8; i++) { S += rs[i]; Q += rq[i]; }
        atomicAdd(&g_sum[bg], S); atomicAdd(&g_sq[bg], Q);
    }
}

// fused GN + Q/K/V convs + ksum; q/k/v stored half, natural [c][px] layout.
__global__ void __launch_bounds__(256, 2) k_qkv(
    const float* __restrict__ x, const float* __restrict__ gamma, const float* __restrict__ beta,
    const float* __restrict__ bq, const float* __restrict__ bk, const float* __restrict__ bv) {
    extern __shared__ __half smh[];
    __half* Xs = smh;                          // [256 k][LDXS]
    __half* Wbuf = smh + 256 * LDXS;           // 2 x [256][LDWS]
    float* sc = (float*)(smh + 256 * LDXS + 2 * 256 * LDWS);   // dedicated
    float* tb = sc + 256;
    int b = blockIdx.y, p0 = blockIdx.x * 64;
    int tid = threadIdx.x, lane = tid & 31, warp = tid >> 5;
    int wo = warp & 3, wp = warp >> 2, c2 = lane & 3;
    uint32_t xs = (uint32_t)__cvta_generic_to_shared(Xs);
    {
        int c = tid, g = c >> 5;
        float mean = g_sum[b * 8 + g] * (1.0f / NG_);
        float var = g_sq[b * 8 + g] * (1.0f / NG_) - mean * mean;
        float s = rsqrtf(var + 1e-5f) * gamma[c];
        sc[c] = s; tb[c] = beta[c] - mean * s;
    }
    __syncthreads();
#pragma unroll
    for (int i = 0; i < 16; i++) {
        int lin = i * 256 + tid, c = lin >> 4, px = (lin & 15) << 2;
        float4 v = *(const float4*)(x + ((size_t)(b * C_ + c)) * HW_ + p0 + px);
        float s = sc[c], t = tb[c];
        *(half2*)(Xs + c * LDXS + px) = __floats2half2_rn(fmaf(v.x, s, t), fmaf(v.y, s, t));
        *(half2*)(Xs + c * LDXS + px + 2) = __floats2half2_rn(fmaf(v.z, s, t), fmaf(v.w, s, t));
    }
    __syncthreads();
    float acc[4][4][4];
    // ---- Q ----
    gemm_h(g_Wh, xs, Wbuf, tid, lane, wo, wp, acc);
#pragma unroll
    for (int m = 0; m < 4; m++) {
        int row = wo * 64 + m * 16 + (lane >> 2);
        float b0 = bq[row], b1 = bq[row + 8];
        size_t o0 = ((size_t)(b * C_ + row)) * HW_ + p0;
        size_t o1 = ((size_t)(b * C_ + row + 8)) * HW_ + p0;
#pragma unroll
        for (int n = 0; n < 4; n++) {
            int col = wp * 32 + n * 8 + (c2 << 1);
            *(half2*)(g_q + o0 + col) = __floats2half2_rn(elu1(acc[m][n][0] + b0), elu1(acc[m][n][1] + b0));
            *(half2*)(g_q + o1 + col) = __floats2half2_rn(elu1(acc[m][n][2] + b1), elu1(acc[m][n][3] + b1));
        }
    }
    // ---- K + fused ksum (sum of the ROUNDED halves for consistency with kv) ----
    gemm_h(g_Wh + 65536, xs, Wbuf, tid, lane, wo, wp, acc);
#pragma unroll
    for (int m = 0; m < 4; m++) {
        int row = wo * 64 + m * 16 + (lane >> 2);
        float b0 = bk[row], b1 = bk[row + 8];
        size_t o0 = ((size_t)(b * C_ + row)) * HW_ + p0;
        size_t o1 = ((size_t)(b * C_ + row + 8)) * HW_ + p0;
        float s0 = 0.f, s1 = 0.f;
#pragma unroll
        for (int n = 0; n < 4; n++) {
            int col = wp * 32 + n * 8 + (c2 << 1);
            half2 h0 = __floats2half2_rn(elu1(acc[m][n][0] + b0), elu1(acc[m][n][1] + b0));
            half2 h1 = __floats2half2_rn(elu1(acc[m][n][2] + b1), elu1(acc[m][n][3] + b1));
            *(half2*)(g_k + o0 + col) = h0;
            *(half2*)(g_k + o1 + col) = h1;
            s0 += __low2float(h0) + __high2float(h0);
            s1 += __low2float(h1) + __high2float(h1);
        }
        s0 += __shfl_xor_sync(~0u, s0, 1); s0 += __shfl_xor_sync(~0u, s0, 2);
        s1 += __shfl_xor_sync(~0u, s1, 1); s1 += __shfl_xor_sync(~0u, s1, 2);
        if (c2 == 0) {
            atomicAdd(&g_ksum[b * C_ + row], s0);
            atomicAdd(&g_ksum[b * C_ + row + 8], s1);
        }
    }
    // ---- V ----
    gemm_h(g_Wh + 131072, xs, Wbuf, tid, lane, wo, wp, acc);
#pragma unroll
    for (int m = 0; m < 4; m++) {
        int row = wo * 64 + m * 16 + (lane >> 2);
        float b0 = bv[row], b1 = bv[row + 8];
        size_t o0 = ((size_t)(b * C_ + row)) * HW_ + p0;
        size_t o1 = ((size_t)(b * C_ + row + 8)) * HW_ + p0;
#pragma unroll
        for (int n = 0; n < 4; n++) {
            int col = wp * 32 + n * 8 + (c2 << 1);
            *(half2*)(g_v + o0 + col) = __floats2half2_rn(acc[m][n][0] + b0, acc[m][n][1] + b0);
            *(half2*)(g_v + o1 + col) = __floats2half2_rn(acc[m][n][2] + b1, acc[m][n][3] + b1);
        }
    }
}

// kv split-K: A = k[c][px] (ldmatrix non-trans), B = v[d][px] (ldmatrix non-trans).
__device__ __forceinline__ void kv_issue(__half* Kt, __half* Vt, int b, int cv0, int p0, int tid) {
#pragma unroll
    for (int i = 0; i < 4; i++) {
        int lin = i * 256 + tid, row = lin >> 2, seg = lin & 3;
        cp16(Kt + row * LDWS + seg * 8, g_k + ((size_t)(b * C_ + row)) * HW_ + p0 + seg * 8);
    }
    {
        int row = tid >> 2, seg = tid & 3;
        cp16(Vt + row * LDWS + seg * 8, g_v + ((size_t)(b * C_ + cv0 + row)) * HW_ + p0 + seg * 8);
    }
    CP_COMMIT();
}

__global__ void __launch_bounds__(256, 2) k_kv() {
    extern __shared__ __half smh[];
    const int TSZ = 320 * LDWS;   // K tile 256 rows + V tile 64 rows
    int s = blockIdx.x >> 2, cvt = blockIdx.x & 3, b = blockIdx.y;
    int cv0 = cvt * 64;
    int tid = threadIdx.x, lane = tid & 31, warp = tid >> 5;
    int wo = warp & 3, wp = warp >> 2, c2 = lane & 3;
    int rowA = lane & 15, colA = (lane & 16) >> 1;
    int rowB = (lane & 7) + ((lane & 16) >> 1), colB = lane & 8;
    float acc[4][4][4];
#pragma unroll
    for (int m = 0; m < 4; m++)
#pragma unroll
        for (int n = 0; n < 4; n++)
#pragma unroll
            for (int i = 0; i < 4; i++) acc[m][n][i] = 0.f;
    kv_issue(smh, smh + 256 * LDWS, b, cv0, s * 1024, tid);
    for (int ch = 0; ch < 32; ch++) {
        if (ch < 31) {
            __half* nb = smh + ((ch + 1) & 1) * TSZ;
            kv_issue(nb, nb + 256 * LDWS, b, cv0, s * 1024 + (ch + 1) * 32, tid);
            CP_WAIT1();
        } else {
            CP_WAIT0();
        }
        __syncthreads();
        uint32_t kt = (uint32_t)__cvta_generic_to_shared(smh + (ch & 1) * TSZ);
        uint32_t vt = kt + 256 * LDWS * 2;
#pragma unroll
        for (int ks = 0; ks < 2; ks++) {
            uint32_t A[4][4];
#pragma unroll
            for (int m = 0; m < 4; m++)
                ldsm4(A[m], kt + ((wo * 64 + m * 16 + rowA) * LDWS + ks * 16 + colA) * 2);
            uint32_t Bv[2][4];
#pragma unroll
            for (int t = 0; t < 2; t++)
                ldsm4(Bv[t], vt + ((wp * 32 + t * 16 + rowB) * LDWS + ks * 16 + colB) * 2);
#pragma unroll
            for (int m = 0; m < 4; m++)
#pragma unroll
                for (int n = 0; n < 4; n++)
                    mma16(acc[m][n], A[m], Bv[n >> 1][(n & 1) * 2], Bv[n >> 1][(n & 1) * 2 + 1]);
        }
        __syncthreads();
    }
    float* outp = g_kvp + ((size_t)(b * 16 + s)) * C_ * C_;
#pragma unroll
    for (int m = 0; m < 4; m++) {
        int row = wo * 64 + m * 16 + (lane >> 2);
#pragma unroll
        for (int n = 0; n < 4; n++) {
            int col = cv0 + wp * 32 + n * 8 + (c2 << 1);
            *(float2*)(outp + row * C_ + col) = make_float2(acc[m][n][0], acc[m][n][1]);
            *(float2*)(outp + (row + 8) * C_ + col) = make_float2(acc[m][n][2], acc[m][n][3]);
        }
    }
}

__global__ void __launch_bounds__(64) k_red() {
    int ck = blockIdx.x, b = blockIdx.y, cv4 = threadIdx.x * 4;
    float4 s = make_float4(0.f, 0.f, 0.f, 0.f);
    for (int sp = 0; sp < 16; sp++) {
        float4 v = *(const float4*)(g_kvp + ((size_t)(b * 16 + sp) * C_ + ck) * C_ + cv4);
        s.x += v.x; s.y += v.y; s.z += v.z; s.w += v.w;
    }
    float inv = 1.0f / (g_ksum[b * C_ + ck] + 1e-6f);
    s.x *= inv; s.y *= inv; s.z *= inv; s.w *= inv;
    *(float4*)(g_kvn + (size_t)(b * C_ + ck) * C_ + cv4) = s;
}

// M[b] = Wp @ kvn[b]; kvn used as B[k=c][n=d] (natural layout), M stored half [o][d].
__global__ void __launch_bounds__(256, 2) k_m() {
    extern __shared__ __half smh[];
    __half* Xs = smh;
    __half* Wbuf = smh + 256 * LDXS;
    int b = blockIdx.y, d0 = blockIdx.x * 64;
    int tid = threadIdx.x, lane = tid & 31, warp = tid >> 5;
    int wo = warp & 3, wp_ = warp >> 2, c2 = lane & 3;
    uint32_t xs = (uint32_t)__cvta_generic_to_shared(Xs);
#pragma unroll
    for (int i = 0; i < 16; i++) {
        int lin = i * 256 + tid, c = lin >> 4, d4 = (lin & 15) << 2;
        float4 v = *(const float4*)(g_kvn + (size_t)(b * C_ + c) * C_ + d0 + d4);
        *(half2*)(Xs + c * LDXS + d4) = __floats2half2_rn(v.x, v.y);
        *(half2*)(Xs + c * LDXS + d4 + 2) = __floats2half2_rn(v.z, v.w);
    }
    __syncthreads();
    float acc[4][4][4];
    gemm_h(g_Wh + 196608, xs, Wbuf, tid, lane, wo, wp_, acc);
    __half* outp = g_M + (size_t)b * 65536;
#pragma unroll
    for (int m = 0; m < 4; m++) {
        int row = wo * 64 + m * 16 + (lane >> 2);
#pragma unroll
        for (int n = 0; n < 4; n++) {
            int col = d0 + wp_ * 32 + n * 8 + (c2 << 1);
            *(half2*)(outp + row * C_ + col) = __floats2half2_rn(acc[m][n][0], acc[m][n][1]);
            *(half2*)(outp + (row + 8) * C_ + col) = __floats2half2_rn(acc[m][n][2], acc[m][n][3]);
        }
    }
}

// out = M @ q + bp + x;  q used as B[k=d][n=px] (natural layout)
__global__ void __launch_bounds__(256, 2) k_out(const float* __restrict__ x,
                                                const float* __restrict__ bp, float* __restrict__ out) {
    extern __shared__ __half smh[];
    __half* Xs = smh;
    __half* Wbuf = smh + 256 * LDXS;
    int b = blockIdx.y, p0 = blockIdx.x * 64;
    int tid = threadIdx.x, lane = tid & 31, warp = tid >> 5;
    int wo = warp & 3, wp = warp >> 2, c2 = lane & 3;
    uint32_t xs = (uint32_t)__cvta_generic_to_shared(Xs);
#pragma unroll
    for (int i = 0; i < 8; i++) {
        int lin = i * 256 + tid, d = lin >> 3, px = (lin & 7) << 3;
        uint4 v = *(const uint4*)(g_q + ((size_t)(b * C_ + d)) * HW_ + p0 + px);
        *(uint4*)(Xs + d * LDXS + px) = v;
    }
    __syncthreads();
    float acc[4][4][4];
    gemm_h(g_M + (size_t)b * 65536, xs, Wbuf, tid, lane, wo, wp, acc);
#pragma unroll
    for (int m = 0; m < 4; m++) {
        int row = wo * 64 + m * 16 + (lane >> 2);
        float b0 = bp[row], b1 = bp[row + 8];
        size_t o0 = ((size_t)(b * C_ + row)) * HW_ + p0;
        size_t o1 = ((size_t)(b * C_ + row + 8)) * HW_ + p0;
#pragma unroll
        for (int n = 0; n < 4; n++) {
            int col = wp * 32 + n * 8 + (c2 << 1);
            float2 x0 = *(const float2*)(x + o0 + col);
            float2 x1 = *(const float2*)(x + o1 + col);
            *(float2*)(out + o0 + col) = make_float2(acc[m][n][0] + b0 + x0.x, acc[m][n][1] + b0 + x0.y);
            *(float2*)(out + o1 + col) = make_float2(acc[m][n][2] + b1 + x1.x, acc[m][n][3] + b1 + x1.y);
        }
    }
}

extern "C" void kernel_launch(void* const* d_in, const int* in_sizes, int n_in,
                              void* d_out, int out_size) {
    const float* x = (const float*)d_in[0];
    const float* gamma = (const float*)d_in[1];
    const float* beta = (const float*)d_in[2];
    const float* Wq = (const float*)d_in[3];
    const float* bq = (const float*)d_in[4];
    const float* Wk = (const float*)d_in[5];
    const float* bk = (const float*)d_in[6];
    const float* Wv = (const float*)d_in[7];
    const float* bv = (const float*)d_in[8];
    const float* Wp = (const float*)d_in[9];
    const float* bp = (const float*)d_in[10];
    float* out = (float*)d_out;

    const int SMEM_QKV = (256 * LDXS + 2 * 256 * LDWS) * 2 + 2048;  // 79872 B
    const int SMEM_GEMM = (256 * LDXS + 2 * 256 * LDWS) * 2;        // 77824 B
    const int SMEM_KV = 2 * 320 * LDWS * 2;                          // 51200 B
    cudaFuncSetAttribute(k_qkv, cudaFuncAttributeMaxDynamicSharedMemorySize, SMEM_QKV);
    cudaFuncSetAttribute(k_m, cudaFuncAttributeMaxDynamicSharedMemorySize, SMEM_GEMM);
    cudaFuncSetAttribute(k_out, cudaFuncAttributeMaxDynamicSharedMemorySize, SMEM_GEMM);
    cudaFuncSetAttribute(k_kv, cudaFuncAttributeMaxDynamicSharedMemorySize, SMEM_KV);

    k0_zero<<<8, 256>>>();
    k_prep<<<256, 256>>>(Wq, Wk, Wv, Wp);
    k_stats<<<dim3(16, 64), 256>>>(x);
    k_qkv<<<dim3(256, 8), 256, SMEM_QKV>>>(x, gamma, beta, bq, bk, bv);
    k_kv<<<dim3(64, 8), 256, SMEM_KV>>>();
    k_red<<<dim3(256, 8), 64>>>();
    k_m<<<dim3(4, 8), 256, SMEM_GEMM>>>();
    k_out<<<dim3(256, 8), 256, SMEM_GEMM>>>(x, bp, out);
}